// round 16
// baseline (speedup 1.0000x reference)
#include <cuda_runtime.h>
#include <math.h>
#include <stdint.h>

#define EPSQ 1e-8f
#define NEGINF (-__int_as_float(0x7f800000))

// row-normalized codebook, fp32 [1024][256]
__device__ float g_cbs[1024 * 256];

// ---- prep: normalize codebook rows -> g_cbs ----
__global__ void prep_codebook(const float* __restrict__ cb, int K) {
    int row = blockIdx.x * 8 + (threadIdx.x >> 5);
    int lane = threadIdx.x & 31;
    if (row >= K) return;
    const float4* src = (const float4*)(cb + (size_t)row * 256);
    float4 a = src[lane * 2], b = src[lane * 2 + 1];
    float ss = a.x*a.x + a.y*a.y + a.z*a.z + a.w*a.w + b.x*b.x + b.y*b.y + b.z*b.z + b.w*b.w;
#pragma unroll
    for (int off = 16; off; off >>= 1) ss += __shfl_xor_sync(0xffffffffu, ss, off);
    float inv = 1.0f / fmaxf(sqrtf(ss), EPSQ);
    float4* dst = (float4*)(g_cbs + (size_t)row * 256);
    a.x *= inv; a.y *= inv; a.z *= inv; a.w *= inv;
    b.x *= inv; b.y *= inv; b.z *= inv; b.w *= inv;
    dst[lane * 2] = a;
    dst[lane * 2 + 1] = b;
}

// Verify up to 4 candidates at once: interleaved codebook loads (4x MLP) and
// 4 independent shuffle-reduce chains. Exact fp32 dot + accurate logf chain
// (identical arithmetic to R15's verified path).
__device__ __forceinline__ void proc4(int n, int k0, int k1, int k2, int k3,
                                      float u0, float u1, float u2, float u3,
                                      float4 a0, float4 a1, float sc,
                                      float& best, int& bkk, int lane) {
    int ks[4] = {k0, k1, k2, k3};
    float us[4] = {u0, u1, u2, u3};
    float d[4] = {0.0f, 0.0f, 0.0f, 0.0f};
#pragma unroll
    for (int i = 0; i < 4; i++)
        if (i < n) {
            const float4* b4 = (const float4*)(g_cbs + (size_t)ks[i] * 256);
            float4 b0 = b4[lane], b1 = b4[32 + lane];
            d[i] = a0.x*b0.x + a0.y*b0.y + a0.z*b0.z + a0.w*b0.w
                 + a1.x*b1.x + a1.y*b1.y + a1.z*b1.z + a1.w*b1.w;
        }
#pragma unroll
    for (int off = 16; off; off >>= 1) {
#pragma unroll
        for (int i = 0; i < 4; i++) d[i] += __shfl_xor_sync(0xffffffffu, d[i], off);
    }
#pragma unroll
    for (int i = 0; i < 4; i++)
        if (i < n) {
            float g = -logf(-logf(us[i]));
            float lg = fmaf(d[i], sc, g);
            if (lg > best || (lg == best && ks[i] < bkk)) { best = lg; bkk = ks[i]; }
        }
}

// ---- main: one warp per row. Gumbel-dominance screen, batched exact verify. ----
__global__ void __launch_bounds__(256)
quant_screen(const float* __restrict__ latent, const float* __restrict__ noise,
             const float* __restrict__ cb, const float* __restrict__ tptr,
             float* __restrict__ out, int K) {
    const int lane = threadIdx.x & 31;
    const int warp = threadIdx.x >> 5;
    const size_t row = (size_t)blockIdx.x * 8 + warp;

    const float4* u4 = (const float4*)(noise + row * (size_t)K);
    const float4* l4 = (const float4*)(latent + row * 256);

    // latent row loads issued early (overlap with noise stream)
    float4 a0 = l4[lane], a1 = l4[32 + lane];

    // pass 1: stream noise row, running max ONLY (asm loads: no CSE, no v[8] regs)
    float m = 0.0f;
#pragma unroll
    for (int j = 0; j < 8; j++) {
        float4 x;
        const float4* p = u4 + j * 32 + lane;
        asm volatile("ld.global.v4.f32 {%0,%1,%2,%3}, [%4];"
                     : "=f"(x.x), "=f"(x.y), "=f"(x.z), "=f"(x.w) : "l"(p));
        m = fmaxf(m, fmaxf(fmaxf(x.x, x.y), fmaxf(x.z, x.w)));
    }
    float ss = a0.x*a0.x + a0.y*a0.y + a0.z*a0.z + a0.w*a0.w
             + a1.x*a1.x + a1.y*a1.y + a1.z*a1.z + a1.w*a1.w;
    // interleaved reductions (two independent shuffle chains)
#pragma unroll
    for (int off = 16; off; off >>= 1) {
        m = fmaxf(m, __shfl_xor_sync(0xffffffffu, m, off));
        ss += __shfl_xor_sync(0xffffffffu, ss, off);
    }
    float temp = *tptr;
    float sc = 1.0f / (fmaxf(sqrtf(ss), EPSQ) * temp);

    // threshold in w = 1-u space (fp32-robust near u=1); validated R15.
    float wmax = 1.0f - m;
    float nlu = -log1pf(-wmax);                  // -ln(umax)
    float margin = (2.0f / temp) * 1.0001f + 0.03f;
    float em = expf(margin);
    float wthr = -expm1f(-em * nlu);             // 1 - uthr
    float uthr = fminf(1.0f - wthr, m);          // umax always a candidate

    // pass 2: re-read noise (L1 hits), ballot candidates, batch-verify x4
    float best = NEGINF;
    int bkk = 0x7fffffff;
    int pk0 = 0, pk1 = 0, pk2 = 0, pk3 = 0;
    float pu0 = 0.5f, pu1 = 0.5f, pu2 = 0.5f, pu3 = 0.5f;
    int pc = 0;
#pragma unroll
    for (int j = 0; j < 8; j++) {
        float4 x = u4[j * 32 + lane];
        float uu[4] = {x.x, x.y, x.z, x.w};
#pragma unroll
        for (int t = 0; t < 4; t++) {
            unsigned mask = __ballot_sync(0xffffffffu, uu[t] >= uthr);
            while (mask) {
                int L = __ffs(mask) - 1;
                mask &= mask - 1;
                float uv = __shfl_sync(0xffffffffu, uu[t], L);
                int k = j * 128 + L * 4 + t;
                if (pc == 0)      { pk0 = k; pu0 = uv; }
                else if (pc == 1) { pk1 = k; pu1 = uv; }
                else if (pc == 2) { pk2 = k; pu2 = uv; }
                else              { pk3 = k; pu3 = uv; }
                if (++pc == 4) {
                    proc4(4, pk0, pk1, pk2, pk3, pu0, pu1, pu2, pu3,
                          a0, a1, sc, best, bkk, lane);
                    pc = 0;
                }
            }
        }
    }
    if (pc > 0)
        proc4(pc, pk0, pk1, pk2, pk3, pu0, pu1, pu2, pu3, a0, a1, sc, best, bkk, lane);

    // gather winner row from ORIGINAL codebook
    const float4* c4 = (const float4*)(cb + (size_t)bkk * 256);
    float4* o4 = (float4*)(out + row * 256);
    o4[lane] = c4[lane];
    o4[32 + lane] = c4[32 + lane];
}

extern "C" void kernel_launch(void* const* d_in, const int* in_sizes, int n_in,
                              void* d_out, int out_size) {
    const float* latent = (const float*)d_in[0];
    const float* noise  = (const float*)d_in[1];
    const float* cb     = (const float*)d_in[2];
    const float* tptr   = (const float*)d_in[3];

    double s0 = (double)in_sizes[0], s1 = (double)in_sizes[1], s2 = (double)in_sizes[2];
    int D = (int)llround(sqrt(s0 * s2 / s1));   // 256
    int K = in_sizes[2] / D;                    // 1024
    int N = in_sizes[0] / D;                    // 131072

    prep_codebook<<<K / 8, 256>>>(cb, K);
    quant_screen<<<N / 8, 256>>>(latent, noise, cb, tptr, (float*)d_out, K);
}

// round 17
// speedup vs baseline: 4.7924x; 4.7924x over previous
#include <cuda_runtime.h>
#include <math.h>
#include <stdint.h>

#define EPSQ 1e-8f
#define NEGINF (-__int_as_float(0x7f800000))

// row-normalized codebook, fp32 [1024][256]
__device__ float g_cbs[1024 * 256];

// ---- prep: normalize codebook rows -> g_cbs ----
__global__ void prep_codebook(const float* __restrict__ cb, int K) {
    int row = blockIdx.x * 8 + (threadIdx.x >> 5);
    int lane = threadIdx.x & 31;
    if (row >= K) return;
    const float4* src = (const float4*)(cb + (size_t)row * 256);
    float4 a = src[lane * 2], b = src[lane * 2 + 1];
    float ss = a.x*a.x + a.y*a.y + a.z*a.z + a.w*a.w + b.x*b.x + b.y*b.y + b.z*b.z + b.w*b.w;
#pragma unroll
    for (int off = 16; off; off >>= 1) ss += __shfl_xor_sync(0xffffffffu, ss, off);
    float inv = 1.0f / fmaxf(sqrtf(ss), EPSQ);
    float4* dst = (float4*)(g_cbs + (size_t)row * 256);
    a.x *= inv; a.y *= inv; a.z *= inv; a.w *= inv;
    b.x *= inv; b.y *= inv; b.z *= inv; b.w *= inv;
    dst[lane * 2] = a;
    dst[lane * 2 + 1] = b;
}

// ---- main: one warp per row, 2 warps per CTA (fine-grain slot recycling). ----
// Gumbel-dominance screening (rigorous Cauchy-Schwarz bound), exact fp32 verify.
// Identical math to the R15 kernel that measured rel_err 0.0 at 382us.
__global__ void __launch_bounds__(64)
quant_screen(const float* __restrict__ latent, const float* __restrict__ noise,
             const float* __restrict__ cb, const float* __restrict__ tptr,
             float* __restrict__ out, int K) {
    const int lane = threadIdx.x & 31;
    const int warp = threadIdx.x >> 5;
    const size_t row = (size_t)blockIdx.x * 2 + warp;

    const float4* u4 = (const float4*)(noise + row * (size_t)K);
    const float4* l4 = (const float4*)(latent + row * 256);

    // latent loads issued early; overlap with the noise stream
    float4 a0 = l4[lane], a1 = l4[32 + lane];

    // 1) stream the noise row into registers, running per-lane max
    float4 v[8];
    float m = 0.0f;
#pragma unroll
    for (int j = 0; j < 8; j++) {
        v[j] = u4[j * 32 + lane];
        m = fmaxf(m, fmaxf(fmaxf(v[j].x, v[j].y), fmaxf(v[j].z, v[j].w)));
    }
    float ss = a0.x*a0.x + a0.y*a0.y + a0.z*a0.z + a0.w*a0.w
             + a1.x*a1.x + a1.y*a1.y + a1.z*a1.z + a1.w*a1.w;
    // two independent shuffle-reduce chains, interleaved
#pragma unroll
    for (int off = 16; off; off >>= 1) {
        m = fmaxf(m, __shfl_xor_sync(0xffffffffu, m, off));
        ss += __shfl_xor_sync(0xffffffffu, ss, off);
    }
    float temp = *tptr;
    float sc = 1.0f / (fmaxf(sqrtf(ss), EPSQ) * temp);

    // 2) threshold in w = 1-u space (fp32-robust near u=1); validated R15.
    //    winner must have gumbel >= gmax - 2/temp (|cos/temp| <= 1/temp exactly).
    float wmax = 1.0f - m;                       // exact (Sterbenz) for m >= 0.5
    float nlu = -log1pf(-wmax);                  // -ln(umax), accurate near 1
    float margin = (2.0f / temp) * 1.0001f + 0.03f;
    float em = expf(margin);
    float wthr = -expm1f(-em * nlu);             // 1 - uthr, accurate
    float uthr = fminf(1.0f - wthr, m);          // clamp: umax always a candidate

    // 3) scan slots; for each candidate, warp-cooperative exact fp32 logit
    float best = NEGINF;
    int bkk = 0x7fffffff;
#pragma unroll
    for (int j = 0; j < 8; j++) {
        float uu[4] = {v[j].x, v[j].y, v[j].z, v[j].w};
#pragma unroll
        for (int t = 0; t < 4; t++) {
            unsigned mask = __ballot_sync(0xffffffffu, uu[t] >= uthr);
            while (mask) {
                int L = __ffs(mask) - 1;
                mask &= mask - 1;
                float uv = __shfl_sync(0xffffffffu, uu[t], L);
                int k = j * 128 + L * 4 + t;
                const float4* b4 = (const float4*)(g_cbs + (size_t)k * 256);
                float4 b0 = b4[lane], b1 = b4[32 + lane];
                float d = a0.x*b0.x + a0.y*b0.y + a0.z*b0.z + a0.w*b0.w
                        + a1.x*b1.x + a1.y*b1.y + a1.z*b1.z + a1.w*b1.w;
#pragma unroll
                for (int off = 16; off; off >>= 1) d += __shfl_xor_sync(0xffffffffu, d, off);
                float g = -logf(-logf(uv));      // accurate chain (reference semantics)
                float lg = fmaf(d, sc, g);
                if (lg > best || (lg == best && k < bkk)) { best = lg; bkk = k; }
            }
        }
    }

    // 4) gather winner row from ORIGINAL codebook
    const float4* c4 = (const float4*)(cb + (size_t)bkk * 256);
    float4* o4 = (float4*)(out + row * 256);
    o4[lane] = c4[lane];
    o4[32 + lane] = c4[32 + lane];
}

extern "C" void kernel_launch(void* const* d_in, const int* in_sizes, int n_in,
                              void* d_out, int out_size) {
    const float* latent = (const float*)d_in[0];
    const float* noise  = (const float*)d_in[1];
    const float* cb     = (const float*)d_in[2];
    const float* tptr   = (const float*)d_in[3];

    double s0 = (double)in_sizes[0], s1 = (double)in_sizes[1], s2 = (double)in_sizes[2];
    int D = (int)llround(sqrt(s0 * s2 / s1));   // 256
    int K = in_sizes[2] / D;                    // 1024
    int N = in_sizes[0] / D;                    // 131072

    prep_codebook<<<K / 8, 256>>>(cb, K);
    quant_screen<<<N / 2, 64>>>(latent, noise, cb, tptr, (float*)d_out, K);
}